// round 8
// baseline (speedup 1.0000x reference)
#include <cuda_runtime.h>
#include <stdint.h>

// ProbabilisticPrediction fused kernel, R8: R=2 rows/block, 512 threads,
// grid=512, launch_bounds(512,3) => <=42 regs, ~3 blocks/SM resident (75% occ)
// for latency hiding. MUFU lg2 Gumbel, f-gather hidden under layer1 q-part,
// eps precomputed into a register, merged layer3 reduce+sample tail.
// Gumbel-argmax (JAX threefry partitionable) selects one mixture component
// per (b,q); the 3-layer MLP is evaluated only at those 1024 points.

#define B_   4
#define QL_  256
#define CL_  512
#define DIM_ 128
#define YD_  16
#define R_   2

// ---------------------------------------------------------------- threefry2x32
__host__ __device__ inline void tf2x32(uint32_t k0, uint32_t k1,
                                       uint32_t c0, uint32_t c1,
                                       uint32_t& o0, uint32_t& o1) {
    uint32_t k2 = k0 ^ k1 ^ 0x1BD11BDAu;
    uint32_t x0 = c0 + k0, x1 = c1 + k1;
#define TFR(d) do { x0 += x1; x1 = (x1 << (d)) | (x1 >> (32 - (d))); x1 ^= x0; } while (0)
    TFR(13); TFR(15); TFR(26); TFR(6);   x0 += k1; x1 += k2 + 1u;
    TFR(17); TFR(29); TFR(16); TFR(24);  x0 += k2; x1 += k0 + 2u;
    TFR(13); TFR(15); TFR(26); TFR(6);   x0 += k0; x1 += k1 + 3u;
    TFR(17); TFR(29); TFR(16); TFR(24);  x0 += k1; x1 += k2 + 4u;
    TFR(13); TFR(15); TFR(26); TFR(6);   x0 += k2; x1 += k0 + 5u;
#undef TFR
    o0 = x0; o1 = x1;
}

__device__ inline uint32_t jax_bits(uint32_t k0, uint32_t k1, uint32_t j) {
    uint32_t o0, o1;
    tf2x32(k0, k1, 0u, j, o0, o1);   // partitionable: 64-bit iota (0, j)
    return o0 ^ o1;
}

__device__ inline float bits_to_unit(uint32_t b) {      // [0, 1)
    return __uint_as_float((b >> 9) | 0x3f800000u) - 1.0f;
}

// XLA ErfInv32 (Giles) -- matches jax.random.normal exactly.
__device__ inline float erfinv_xla(float x) {
    float w = -log1pf(-x * x);
    float p;
    if (w < 5.0f) {
        w -= 2.5f;
        p =            2.81022636e-08f;
        p = fmaf(p, w, 3.43273939e-07f);
        p = fmaf(p, w, -3.5233877e-06f);
        p = fmaf(p, w, -4.39150654e-06f);
        p = fmaf(p, w, 0.00021858087f);
        p = fmaf(p, w, -0.00125372503f);
        p = fmaf(p, w, -0.00417768164f);
        p = fmaf(p, w, 0.246640727f);
        p = fmaf(p, w, 1.50140941f);
    } else {
        w = sqrtf(w) - 3.0f;
        p =            -0.000200214257f;
        p = fmaf(p, w, 0.000100950558f);
        p = fmaf(p, w, 0.00134934322f);
        p = fmaf(p, w, -0.00367342844f);
        p = fmaf(p, w, 0.00573950773f);
        p = fmaf(p, w, -0.0076224613f);
        p = fmaf(p, w, 0.00943887047f);
        p = fmaf(p, w, 1.00167406f);
        p = fmaf(p, w, 2.83297682f);
    }
    return p * x;
}

// ---------------------------------------------------------------------- kernel
__global__ __launch_bounds__(512, 3)
void pp_fused_kernel(const float* __restrict__ q,
                     const float* __restrict__ f_embed,
                     const float* __restrict__ att_logits,
                     const float* __restrict__ W1q,
                     const float* __restrict__ W1f,
                     const float* __restrict__ b1,
                     const float* __restrict__ W2,
                     const float* __restrict__ b2,
                     const float* __restrict__ Wout,
                     const float* __restrict__ bout,
                     float* __restrict__ out,
                     uint32_t kc0, uint32_t kc1,
                     uint32_t ke0, uint32_t ke1)
{
    const int t   = threadIdx.x;         // 0..511
    const int w   = t >> 5;              // warp 0..15
    const int ln  = t & 31;
    const int bq0 = blockIdx.x * R_;
    const int b   = bq0 >> 8;            // both rows share b (2 | 256)

    __shared__ float sQ[R_ * DIM_];      // q rows; later h2
    __shared__ float sF[R_ * DIM_];      // selected f rows
    __shared__ float sH[R_ * DIM_];      // h1
    __shared__ float sPar[4 * R_ * DIM_];// partials (4KB); reused in layer3
    __shared__ float sVal[16];
    __shared__ int   sIdxW[16];

    // Prefetch q rows (hidden under phase-1 ALU).
    if (t < 64)
        ((float4*)sQ)[t] = ((const float4*)(q + (size_t)bq0 * DIM_))[t];

    // -------- Phase 1: Gumbel-argmax; row r = w>>3, sub-range sub = w&7 -----
    {
        const int r = w >> 3, sub = w & 7;
        const int bq = bq0 + r;
        const float* lrow = att_logits + (size_t)bq * CL_;
        const float TINY = 1.17549435e-38f;
        float best = -__int_as_float(0x7f800000);
        int bi = 0;
#pragma unroll
        for (int i = 0; i < 2; ++i) {
            int c = sub * 64 + i * 32 + ln;
            uint32_t j = (uint32_t)bq * (uint32_t)CL_ + (uint32_t)c;
            float u = bits_to_unit(jax_bits(kc0, kc1, j));
            u = fmaxf(TINY, u * (1.0f - TINY) + TINY);
            // g = -log(-log(u)) = -ln2*log2(-log2(u)) - ln(ln2)
            float lg1; asm("lg2.approx.f32 %0, %1;" : "=f"(lg1) : "f"(u));
            float L = -lg1;
            float lg2v; asm("lg2.approx.f32 %0, %1;" : "=f"(lg2v) : "f"(L));
            float g = fmaf(-0.693147180559945f, lg2v, 0.366512920581664f);
            float v = g + lrow[c];
            if (v > best || (v == best && c < bi)) { best = v; bi = c; }
        }
#pragma unroll
        for (int off = 16; off; off >>= 1) {
            float v2 = __shfl_xor_sync(0xffffffffu, best, off);
            int   i2 = __shfl_xor_sync(0xffffffffu, bi,   off);
            if (v2 > best || (v2 == best && i2 < bi)) { best = v2; bi = i2; }
        }
        if (ln == 0) { sVal[w] = best; sIdxW[w] = bi; }
    }

    // Precompute eps for the sample stage (held in a register until the end).
    float epsv = 0.f;
    if (t < R_ * YD_) {                  // 32 threads
        uint32_t m = (uint32_t)(bq0 + (t >> 4)) * (uint32_t)YD_ + (uint32_t)(t & 15);
        float u = bits_to_unit(jax_bits(ke0, ke1, m));
        const float lo = -0.99999994f;
        float x = fmaxf(lo, u * (1.0f - lo) + lo);
        epsv = 1.41421356237f * erfinv_xla(x);
    }
    __syncthreads();                     // A: sVal/sIdxW + sQ visible

    // Warps 0-1 finalize their row's argmax and start the f-row gather; the
    // gather's LDG latency hides under the layer-1 q-part below.
    float4 fgv;
    const bool gat = (t < 64);
    if (gat) {
        const int r = w;                 // 0..1
        float bv = sVal[r * 8]; int bj = sIdxW[r * 8];
#pragma unroll
        for (int k = 1; k < 8; ++k) {
            float v2 = sVal[r * 8 + k]; int i2 = sIdxW[r * 8 + k];
            if (v2 > bv || (v2 == bv && i2 < bj)) { bv = v2; bj = i2; }
        }
        fgv = ((const float4*)(f_embed + ((size_t)b * CL_ + bj) * DIM_))[ln];
    }

    const int c   = t & 127;             // output column
    const int oct = t >> 7;              // d-quarter 0..3 (32 d's each)
    float acc0 = 0.f, acc1 = 0.f;

    // -------- Layer 1, q-part: acc += q@W1q ---------------------------------
    {
        const float* wq = W1q + c;
#pragma unroll
        for (int i = 0; i < 8; ++i) {
            const int d = oct * 32 + i * 4;
            float w0 = wq[(d + 0) * DIM_], w1 = wq[(d + 1) * DIM_];
            float w2v = wq[(d + 2) * DIM_], w3 = wq[(d + 3) * DIM_];
            float4 q0 = ((const float4*)sQ)[(d >> 2)];
            float4 q1 = ((const float4*)sQ)[32 + (d >> 2)];
            acc0 = fmaf(q0.x, w0, acc0); acc0 = fmaf(q0.y, w1, acc0);
            acc0 = fmaf(q0.z, w2v, acc0); acc0 = fmaf(q0.w, w3, acc0);
            acc1 = fmaf(q1.x, w0, acc1); acc1 = fmaf(q1.y, w1, acc1);
            acc1 = fmaf(q1.z, w2v, acc1); acc1 = fmaf(q1.w, w3, acc1);
        }
    }
    if (gat) ((float4*)(sF + w * DIM_))[ln] = fgv;
    __syncthreads();                     // B: sF visible

    // -------- Layer 1, f-part: acc += f@W1f; store partials -----------------
    {
        const float* wf = W1f + c;
#pragma unroll
        for (int i = 0; i < 8; ++i) {
            const int d = oct * 32 + i * 4;
            float w0 = wf[(d + 0) * DIM_], w1 = wf[(d + 1) * DIM_];
            float w2v = wf[(d + 2) * DIM_], w3 = wf[(d + 3) * DIM_];
            float4 f0 = ((const float4*)sF)[(d >> 2)];
            float4 f1 = ((const float4*)sF)[32 + (d >> 2)];
            acc0 = fmaf(f0.x, w0, acc0); acc0 = fmaf(f0.y, w1, acc0);
            acc0 = fmaf(f0.z, w2v, acc0); acc0 = fmaf(f0.w, w3, acc0);
            acc1 = fmaf(f1.x, w0, acc1); acc1 = fmaf(f1.y, w1, acc1);
            acc1 = fmaf(f1.z, w2v, acc1); acc1 = fmaf(f1.w, w3, acc1);
        }
        sPar[oct * 256 + 0 * DIM_ + c] = acc0;
        sPar[oct * 256 + 1 * DIM_ + c] = acc1;
    }
    __syncthreads();                     // C
    if (t < 256) {
        float s = sPar[t] + sPar[256 + t] + sPar[512 + t] + sPar[768 + t];
        sH[t] = fmaxf(s + b1[t & 127], 0.f);
    }
    __syncthreads();                     // D

    // -------- Layer 2: h2 = relu(h@W2 + b2) ---------------------------------
    {
        acc0 = 0.f; acc1 = 0.f;
        const float* w2 = W2 + c;
#pragma unroll
        for (int i = 0; i < 8; ++i) {
            const int d = oct * 32 + i * 4;
            float w0 = w2[(d + 0) * DIM_], w1 = w2[(d + 1) * DIM_];
            float w2v = w2[(d + 2) * DIM_], w3 = w2[(d + 3) * DIM_];
            float4 h0 = ((const float4*)sH)[(d >> 2)];
            float4 h1 = ((const float4*)sH)[32 + (d >> 2)];
            acc0 = fmaf(h0.x, w0, acc0); acc0 = fmaf(h0.y, w1, acc0);
            acc0 = fmaf(h0.z, w2v, acc0); acc0 = fmaf(h0.w, w3, acc0);
            acc1 = fmaf(h1.x, w0, acc1); acc1 = fmaf(h1.y, w1, acc1);
            acc1 = fmaf(h1.z, w2v, acc1); acc1 = fmaf(h1.w, w3, acc1);
        }
        sPar[oct * 256 + 0 * DIM_ + c] = acc0;
        sPar[oct * 256 + 1 * DIM_ + c] = acc1;
    }
    __syncthreads();                     // E
    if (t < 256) {
        float s = sPar[t] + sPar[256 + t] + sPar[512 + t] + sPar[768 + t];
        sQ[t] = fmaxf(s + b2[t & 127], 0.f);   // sQ := h2
    }
    __syncthreads();                     // F

    // -------- Layer 3: partials (o = ln, g = w: 8 d's each, both rows) ------
    {
        const int o = ln;                // output column 0..31
        const int g = w;                 // d-group 0..15
        float wv0 = Wout[(g * 8 + 0) * 32 + o], wv1 = Wout[(g * 8 + 1) * 32 + o];
        float wv2 = Wout[(g * 8 + 2) * 32 + o], wv3 = Wout[(g * 8 + 3) * 32 + o];
        float wv4 = Wout[(g * 8 + 4) * 32 + o], wv5 = Wout[(g * 8 + 5) * 32 + o];
        float wv6 = Wout[(g * 8 + 6) * 32 + o], wv7 = Wout[(g * 8 + 7) * 32 + o];
#pragma unroll
        for (int r = 0; r < R_; ++r) {
            float4 h0 = ((const float4*)sQ)[r * 32 + g * 2];
            float4 h1 = ((const float4*)sQ)[r * 32 + g * 2 + 1];
            float a0 = fmaf(h0.x, wv0, fmaf(h0.y, wv1, 0.f));
            float a1 = fmaf(h0.z, wv2, fmaf(h0.w, wv3, 0.f));
            float a2 = fmaf(h1.x, wv4, fmaf(h1.y, wv5, 0.f));
            float a3 = fmaf(h1.z, wv6, fmaf(h1.w, wv7, 0.f));
            sPar[g * 64 + r * 32 + o] = (a0 + a1) + (a2 + a3);
        }
    }
    __syncthreads();                     // G

    // -------- Tail: reduce mu/s + sample (eps precomputed) ------------------
    if (t < R_ * YD_) {                  // 32 threads
        const int rr = t >> 4, y = t & 15;
        float mu = bout[y];
        float sv = bout[YD_ + y];
#pragma unroll
        for (int g = 0; g < 16; ++g) {
            mu += sPar[g * 64 + rr * 32 + y];
            sv += sPar[g * 64 + rr * 32 + YD_ + y];
        }
        float s = fmaxf(-15.0f, sv);
        float sigma = fmaxf(s, 0.0f) + log1pf(expf(-fabsf(s)));
        out[(size_t)bq0 * YD_ + t] = fmaf(sigma, epsv, mu);
    }
}

// ---------------------------------------------------------------------- launch
extern "C" void kernel_launch(void* const* d_in, const int* in_sizes, int n_in,
                              void* d_out, int out_size) {
    const float* q     = (const float*)d_in[0];
    const float* f_emb = (const float*)d_in[1];
    const float* alog  = (const float*)d_in[2];
    const float* W1q   = (const float*)d_in[3];
    const float* W1f   = (const float*)d_in[4];
    const float* b1    = (const float*)d_in[5];
    const float* W2    = (const float*)d_in[6];
    const float* b2    = (const float*)d_in[7];
    const float* Wout  = (const float*)d_in[8];
    const float* bout  = (const float*)d_in[9];
    float* out = (float*)d_out;

    // split(jax.random.key(1), 2), partitionable: subkey_i = tf(key, (0, i))
    uint32_t kc0, kc1, ke0, ke1;
    tf2x32(0u, 1u, 0u, 0u, kc0, kc1);
    tf2x32(0u, 1u, 0u, 1u, ke0, ke1);

    pp_fused_kernel<<<(B_ * QL_) / R_, 512>>>(q, f_emb, alog, W1q, W1f, b1,
                                              W2, b2, Wout, bout, out,
                                              kc0, kc1, ke0, ke1);
}

// round 9
// speedup vs baseline: 1.5009x; 1.5009x over previous
#include <cuda_runtime.h>
#include <stdint.h>

// ProbabilisticPrediction fused kernel, R9 = R6 + weights staged in dynamic
// shared memory (192KB), staging LDGs hidden under phase-1 threefry ALU.
// Layer weight reads become conflict-free scalar LDS; L1/L2 partial buffers
// alias the dead sW1q region. 8 rows/block, 1024 threads, grid 128.
// Gumbel-argmax (JAX threefry partitionable) selects one mixture component
// per (b,q); the 3-layer MLP is evaluated only at those 1024 points.

#define B_   4
#define QL_  256
#define CL_  512
#define DIM_ 128
#define YD_  16
#define R_   8

// float offsets into dynamic smem
#define OFF_W1Q 0
#define OFF_W1F 16384
#define OFF_W2  32768
#define OFF_Q   49152
#define OFF_F   50176
#define OFF_H   51200
#define OFF_P3  52224
#define OFF_VAL 53248
#define OFF_IDX 53280
#define SMEM_FLOATS 53312            // *4 = 213248 bytes

// ---------------------------------------------------------------- threefry2x32
__host__ __device__ inline void tf2x32(uint32_t k0, uint32_t k1,
                                       uint32_t c0, uint32_t c1,
                                       uint32_t& o0, uint32_t& o1) {
    uint32_t k2 = k0 ^ k1 ^ 0x1BD11BDAu;
    uint32_t x0 = c0 + k0, x1 = c1 + k1;
#define TFR(d) do { x0 += x1; x1 = (x1 << (d)) | (x1 >> (32 - (d))); x1 ^= x0; } while (0)
    TFR(13); TFR(15); TFR(26); TFR(6);   x0 += k1; x1 += k2 + 1u;
    TFR(17); TFR(29); TFR(16); TFR(24);  x0 += k2; x1 += k0 + 2u;
    TFR(13); TFR(15); TFR(26); TFR(6);   x0 += k0; x1 += k1 + 3u;
    TFR(17); TFR(29); TFR(16); TFR(24);  x0 += k1; x1 += k2 + 4u;
    TFR(13); TFR(15); TFR(26); TFR(6);   x0 += k2; x1 += k0 + 5u;
#undef TFR
    o0 = x0; o1 = x1;
}

__device__ inline uint32_t jax_bits(uint32_t k0, uint32_t k1, uint32_t j) {
    uint32_t o0, o1;
    tf2x32(k0, k1, 0u, j, o0, o1);   // partitionable: 64-bit iota (0, j)
    return o0 ^ o1;
}

__device__ inline float bits_to_unit(uint32_t b) {      // [0, 1)
    return __uint_as_float((b >> 9) | 0x3f800000u) - 1.0f;
}

// XLA ErfInv32 (Giles) -- matches jax.random.normal exactly.
__device__ inline float erfinv_xla(float x) {
    float w = -log1pf(-x * x);
    float p;
    if (w < 5.0f) {
        w -= 2.5f;
        p =            2.81022636e-08f;
        p = fmaf(p, w, 3.43273939e-07f);
        p = fmaf(p, w, -3.5233877e-06f);
        p = fmaf(p, w, -4.39150654e-06f);
        p = fmaf(p, w, 0.00021858087f);
        p = fmaf(p, w, -0.00125372503f);
        p = fmaf(p, w, -0.00417768164f);
        p = fmaf(p, w, 0.246640727f);
        p = fmaf(p, w, 1.50140941f);
    } else {
        w = sqrtf(w) - 3.0f;
        p =            -0.000200214257f;
        p = fmaf(p, w, 0.000100950558f);
        p = fmaf(p, w, 0.00134934322f);
        p = fmaf(p, w, -0.00367342844f);
        p = fmaf(p, w, 0.00573950773f);
        p = fmaf(p, w, -0.0076224613f);
        p = fmaf(p, w, 0.00943887047f);
        p = fmaf(p, w, 1.00167406f);
        p = fmaf(p, w, 2.83297682f);
    }
    return p * x;
}

// gumbel candidate macro: updates (best, bi) for candidate column c
#define GUMBEL_CAND(c) do {                                                   \
    uint32_t j = (uint32_t)bq * (uint32_t)CL_ + (uint32_t)(c);                \
    float u = bits_to_unit(jax_bits(kc0, kc1, j));                            \
    u = fmaxf(TINY, u * (1.0f - TINY) + TINY);                                \
    float lg1; asm("lg2.approx.f32 %0, %1;" : "=f"(lg1) : "f"(u));            \
    float L = -lg1;                                                           \
    float lg2v; asm("lg2.approx.f32 %0, %1;" : "=f"(lg2v) : "f"(L));          \
    float g = fmaf(-0.693147180559945f, lg2v, 0.366512920581664f);            \
    float v = g + lrow[(c)];                                                  \
    if (v > best || (v == best && (c) < bi)) { best = v; bi = (c); }          \
} while (0)

// ---------------------------------------------------------------------- kernel
__global__ __launch_bounds__(1024, 1)
void pp_fused_kernel(const float* __restrict__ q,
                     const float* __restrict__ f_embed,
                     const float* __restrict__ att_logits,
                     const float* __restrict__ W1q,
                     const float* __restrict__ W1f,
                     const float* __restrict__ b1,
                     const float* __restrict__ W2,
                     const float* __restrict__ b2,
                     const float* __restrict__ Wout,
                     const float* __restrict__ bout,
                     float* __restrict__ out,
                     uint32_t kc0, uint32_t kc1,
                     uint32_t ke0, uint32_t ke1)
{
    extern __shared__ float smem[];
    float4* sm4   = (float4*)smem;
    float*  sW1q  = smem + OFF_W1Q;
    float*  sW1f  = smem + OFF_W1F;
    float*  sW2   = smem + OFF_W2;
    float*  sQ    = smem + OFF_Q;        // q rows; later h2
    float*  sF    = smem + OFF_F;
    float*  sH    = smem + OFF_H;
    float*  sP3   = smem + OFF_P3;
    float*  sVal  = smem + OFF_VAL;
    int*    sIdxW = (int*)(smem + OFF_IDX);
    float*  sPar  = smem;                // alias over sW1q (dead after L1-q)

    const int t   = threadIdx.x;         // 0..1023
    const int w   = t >> 5;              // warp 0..31
    const int ln  = t & 31;
    const int bq0 = blockIdx.x * R_;
    const int b   = bq0 >> 8;            // all R_ rows share b (8 | 256)

    // q prefetch (register; stored to smem before barrier A)
    float4 qpre;
    if (t < 256) qpre = ((const float4*)(q + (size_t)bq0 * DIM_))[t];

    // -------- Staging part A: W1q (4 f4) + first half of W1f (2 f4) --------
    const float4* gW1q4 = (const float4*)W1q;
    const float4* gW1f4 = (const float4*)W1f;
    const float4* gW24  = (const float4*)W2;
    float4 s0 = gW1q4[t],        s1 = gW1q4[t + 1024];
    float4 s2 = gW1q4[t + 2048], s3 = gW1q4[t + 3072];
    float4 s4 = gW1f4[t],        s5 = gW1f4[t + 1024];

    // -------- Phase 1 (chunk 1/2): Gumbel candidates 0-1 --------------------
    const int rr1 = w >> 2, sub = w & 3;
    const int bq = bq0 + rr1;
    const float* lrow = att_logits + (size_t)bq * CL_;
    const float TINY = 1.17549435e-38f;
    float best = -__int_as_float(0x7f800000);
    int bi = 0;
    GUMBEL_CAND(sub * 128 + 0 * 32 + ln);
    GUMBEL_CAND(sub * 128 + 1 * 32 + ln);

    // store staging part A; load part B (rest of W1f + W2)
    sm4[t]         = s0;  sm4[t + 1024] = s1;
    sm4[t + 2048]  = s2;  sm4[t + 3072] = s3;
    sm4[t + 4096]  = s4;  sm4[t + 5120] = s5;
    s0 = gW1f4[t + 2048]; s1 = gW1f4[t + 3072];
    s2 = gW24[t];         s3 = gW24[t + 1024];
    s4 = gW24[t + 2048];  s5 = gW24[t + 3072];

    // -------- Phase 1 (chunk 2/2): candidates 2-3, warp argmax, eps ---------
    GUMBEL_CAND(sub * 128 + 2 * 32 + ln);
    GUMBEL_CAND(sub * 128 + 3 * 32 + ln);
#pragma unroll
    for (int off = 16; off; off >>= 1) {
        float v2 = __shfl_xor_sync(0xffffffffu, best, off);
        int   i2 = __shfl_xor_sync(0xffffffffu, bi,   off);
        if (v2 > best || (v2 == best && i2 < bi)) { best = v2; bi = i2; }
    }
    if (ln == 0) { sVal[w] = best; sIdxW[w] = bi; }

    float epsv = 0.f;
    if (t < R_ * YD_) {                  // 128 threads
        uint32_t m = (uint32_t)(bq0 + (t >> 4)) * (uint32_t)YD_ + (uint32_t)(t & 15);
        float u = bits_to_unit(jax_bits(ke0, ke1, m));
        const float lo = -0.99999994f;
        float x = fmaxf(lo, u * (1.0f - lo) + lo);
        epsv = 1.41421356237f * erfinv_xla(x);
    }

    // store staging part B + q rows
    sm4[t + 6144]  = s0;  sm4[t + 7168]  = s1;
    sm4[t + 8192]  = s2;  sm4[t + 9216]  = s3;
    sm4[t + 10240] = s4;  sm4[t + 11264] = s5;
    if (t < 256) ((float4*)sQ)[t] = qpre;
    __syncthreads();                     // A: weights, sQ, sVal/sIdxW visible

    // Warps 0-7 finalize row argmax and issue the f-row gather; its LDG
    // latency hides under the layer-1 q-part below.
    float4 fgv;
    const bool gat = (t < 256);
    if (gat) {
        const int r = w;                 // 0..7
        float bv = sVal[r * 4]; int bj = sIdxW[r * 4];
#pragma unroll
        for (int k = 1; k < 4; ++k) {
            float v2 = sVal[r * 4 + k]; int i2 = sIdxW[r * 4 + k];
            if (v2 > bv || (v2 == bv && i2 < bj)) { bv = v2; bj = i2; }
        }
        fgv = ((const float4*)(f_embed + ((size_t)b * CL_ + bj) * DIM_))[ln];
    }

    const int c   = t & 127;             // output column
    const int oct = t >> 7;              // d-octant 0..7 (16 d's each)
    float acc[R_];
#pragma unroll
    for (int r = 0; r < R_; ++r) acc[r] = 0.f;

    // -------- Layer 1, q-part: acc += q@W1q (weights via LDS) ---------------
#pragma unroll
    for (int i = 0; i < 4; ++i) {
        const int d = oct * 16 + i * 4;
        float w0 = sW1q[(d + 0) * DIM_ + c], w1 = sW1q[(d + 1) * DIM_ + c];
        float w2v = sW1q[(d + 2) * DIM_ + c], w3 = sW1q[(d + 3) * DIM_ + c];
#pragma unroll
        for (int r = 0; r < R_; ++r) {
            float4 qv = ((const float4*)sQ)[r * 32 + (d >> 2)];
            acc[r] = fmaf(qv.x, w0, acc[r]); acc[r] = fmaf(qv.y, w1, acc[r]);
            acc[r] = fmaf(qv.z, w2v, acc[r]); acc[r] = fmaf(qv.w, w3, acc[r]);
        }
    }
    if (gat) ((float4*)(sF + w * DIM_))[ln] = fgv;
    __syncthreads();                     // B: sF visible; sW1q now dead

    // -------- Layer 1, f-part: acc += f@W1f; partials into sW1q alias -------
#pragma unroll
    for (int i = 0; i < 4; ++i) {
        const int d = oct * 16 + i * 4;
        float w0 = sW1f[(d + 0) * DIM_ + c], w1 = sW1f[(d + 1) * DIM_ + c];
        float w2v = sW1f[(d + 2) * DIM_ + c], w3 = sW1f[(d + 3) * DIM_ + c];
#pragma unroll
        for (int r = 0; r < R_; ++r) {
            float4 fv = ((const float4*)sF)[r * 32 + (d >> 2)];
            acc[r] = fmaf(fv.x, w0, acc[r]); acc[r] = fmaf(fv.y, w1, acc[r]);
            acc[r] = fmaf(fv.z, w2v, acc[r]); acc[r] = fmaf(fv.w, w3, acc[r]);
        }
    }
#pragma unroll
    for (int r = 0; r < R_; ++r) sPar[oct * 1024 + r * DIM_ + c] = acc[r];
    __syncthreads();                     // C
    {
        float s = 0.f;
#pragma unroll
        for (int k = 0; k < 8; ++k) s += sPar[k * 1024 + t];
        sH[t] = fmaxf(s + b1[c], 0.f);
    }
    __syncthreads();                     // D

    // -------- Layer 2: h2 = relu(h@W2 + b2) (weights via LDS) ---------------
#pragma unroll
    for (int r = 0; r < R_; ++r) acc[r] = 0.f;
#pragma unroll
    for (int i = 0; i < 4; ++i) {
        const int d = oct * 16 + i * 4;
        float w0 = sW2[(d + 0) * DIM_ + c], w1 = sW2[(d + 1) * DIM_ + c];
        float w2v = sW2[(d + 2) * DIM_ + c], w3 = sW2[(d + 3) * DIM_ + c];
#pragma unroll
        for (int r = 0; r < R_; ++r) {
            float4 hv = ((const float4*)sH)[r * 32 + (d >> 2)];
            acc[r] = fmaf(hv.x, w0, acc[r]); acc[r] = fmaf(hv.y, w1, acc[r]);
            acc[r] = fmaf(hv.z, w2v, acc[r]); acc[r] = fmaf(hv.w, w3, acc[r]);
        }
    }
#pragma unroll
    for (int r = 0; r < R_; ++r) sPar[oct * 1024 + r * DIM_ + c] = acc[r];
    __syncthreads();                     // E
    {
        float s = 0.f;
#pragma unroll
        for (int k = 0; k < 8; ++k) s += sPar[k * 1024 + t];
        sQ[t] = fmaxf(s + b2[c], 0.f);   // sQ := h2
    }
    __syncthreads();                     // F

    // -------- Layer 3: out = h2@Wout + bout  (4-way d-split, Wout via LDG) --
    {
        const int p  = t >> 8;           // 0..3, d in [p*32, p*32+32)
        const int rr = (t >> 5) & 7;
        const int o  = ln;
        float a0 = 0.f, a1 = 0.f;
#pragma unroll
        for (int d4 = 0; d4 < 8; ++d4) {
            const int d = p * 32 + d4 * 4;
            float4 hv = ((const float4*)sQ)[rr * 32 + (d >> 2)];
            a0 = fmaf(hv.x, Wout[(d + 0) * 32 + o], a0);
            a1 = fmaf(hv.y, Wout[(d + 1) * 32 + o], a1);
            a0 = fmaf(hv.z, Wout[(d + 2) * 32 + o], a0);
            a1 = fmaf(hv.w, Wout[(d + 3) * 32 + o], a1);
        }
        sP3[p * 256 + rr * 32 + o] = a0 + a1;
    }
    __syncthreads();                     // G

    // -------- Tail: reduce mu/s + sample (eps precomputed) ------------------
    if (t < R_ * YD_) {                  // 128 threads
        const int rr = t >> 4, y = t & 15;
        float mu = bout[y];
        float sv = bout[YD_ + y];
#pragma unroll
        for (int p = 0; p < 4; ++p) {
            mu += sP3[p * 256 + rr * 32 + y];
            sv += sP3[p * 256 + rr * 32 + YD_ + y];
        }
        float s = fmaxf(-15.0f, sv);
        float sigma = fmaxf(s, 0.0f) + log1pf(expf(-fabsf(s)));
        out[(size_t)bq0 * YD_ + t] = fmaf(sigma, epsv, mu);
    }
}

// ---------------------------------------------------------------------- launch
extern "C" void kernel_launch(void* const* d_in, const int* in_sizes, int n_in,
                              void* d_out, int out_size) {
    const float* q     = (const float*)d_in[0];
    const float* f_emb = (const float*)d_in[1];
    const float* alog  = (const float*)d_in[2];
    const float* W1q   = (const float*)d_in[3];
    const float* W1f   = (const float*)d_in[4];
    const float* b1    = (const float*)d_in[5];
    const float* W2    = (const float*)d_in[6];
    const float* b2    = (const float*)d_in[7];
    const float* Wout  = (const float*)d_in[8];
    const float* bout  = (const float*)d_in[9];
    float* out = (float*)d_out;

    // split(jax.random.key(1), 2), partitionable: subkey_i = tf(key, (0, i))
    uint32_t kc0, kc1, ke0, ke1;
    tf2x32(0u, 1u, 0u, 0u, kc0, kc1);
    tf2x32(0u, 1u, 0u, 1u, ke0, ke1);

    const int smem_bytes = SMEM_FLOATS * 4;   // 213248
    cudaFuncSetAttribute(pp_fused_kernel,
                         cudaFuncAttributeMaxDynamicSharedMemorySize, smem_bytes);
    pp_fused_kernel<<<(B_ * QL_) / R_, 1024, smem_bytes>>>(
        q, f_emb, alog, W1q, W1f, b1, W2, b2, Wout, bout, out,
        kc0, kc1, ke0, ke1);
}